// round 8
// baseline (speedup 1.0000x reference)
#include <cuda_runtime.h>
#include <cstdint>

// Shape: inp:[2048,2048,3] f32, w_ih:[96,3], w_hh:[96,32], bias:[96], bias_n:[32]
// out:[2048,2048,1] f32 (h[0] each step)
#define TT 2048
#define BB 2048

typedef unsigned long long u64;

__device__ __forceinline__ void ffma2(u64 &d, u64 a, u64 b) {
    asm("fma.rn.f32x2 %0, %1, %2, %0;" : "+l"(d) : "l"(a), "l"(b));
}
__device__ __forceinline__ u64 fma2(u64 a, u64 b, u64 c) {
    u64 d; asm("fma.rn.f32x2 %0, %1, %2, %3;" : "=l"(d) : "l"(a), "l"(b), "l"(c));
    return d;
}
__device__ __forceinline__ u64 add2(u64 a, u64 b) {
    u64 d; asm("add.rn.f32x2 %0, %1, %2;" : "=l"(d) : "l"(a), "l"(b));
    return d;
}
__device__ __forceinline__ u64 mul2(u64 a, u64 b) {
    u64 d; asm("mul.rn.f32x2 %0, %1, %2;" : "=l"(d) : "l"(a), "l"(b));
    return d;
}
__device__ __forceinline__ u64 pack2(float a, float b) {
    u64 d; asm("mov.b64 %0, {%1, %2};" : "=l"(d) : "f"(a), "f"(b));
    return d;
}
__device__ __forceinline__ float2 unpack2(u64 v) {
    float2 r; asm("mov.b64 {%0, %1}, %2;" : "=f"(r.x), "=f"(r.y) : "l"(v));
    return r;
}
__device__ __forceinline__ float tanh_hw(float x) {
    float y; asm("tanh.approx.f32 %0, %1;" : "=f"(y) : "f"(x));
    return y;
}

// One warp per sequence; lane j owns hidden unit j. W_hh in regs (48 f32x2).
// Input gates are computed TWO STEPS AT A TIME as f32x2 with lane-duplicated
// W_ih pairs held in smem (LDS.64 -> MIO pipe, not fma). r/z activations are
// evaluated packed. Every fma-pipe instruction removed is ~1.4% speedup:
// this kernel sits at 97% of the fma rt=2 issue ceiling.
__global__ void __launch_bounds__(32, 14)
gru_warp_kernel(const float* __restrict__ inp,
                const float* __restrict__ w_ih,
                const float* __restrict__ w_hh,
                const float* __restrict__ bias,
                const float* __restrict__ bias_n,
                float* __restrict__ out) {
    __shared__ __align__(16) float hbuf[2][32];
    __shared__ __align__(8)  float xpl[3][32];   // x planes: [dim][step-in-chunk]
    __shared__ u64 wihs[12][32];                 // dup pairs: 9 weights + 3 bias

    const int j = threadIdx.x;
    const int b = blockIdx.x;

    // ---- W_hh rows into registers (dominant cost lives here) ----
    u64 wr[16], wz[16], wa[16];
    {
        const u64* rr = reinterpret_cast<const u64*>(w_hh + (0 * 32 + j) * 32);
        const u64* rz = reinterpret_cast<const u64*>(w_hh + (1 * 32 + j) * 32);
        const u64* ra = reinterpret_cast<const u64*>(w_hh + (2 * 32 + j) * 32);
#pragma unroll
        for (int k = 0; k < 16; k++) { wr[k] = rr[k]; wz[k] = rz[k]; wa[k] = ra[k]; }
    }
    // ---- W_ih + biases as lane-duplicated pairs in smem (own-lane slots) ----
#pragma unroll
    for (int g = 0; g < 3; g++)
#pragma unroll
        for (int d = 0; d < 3; d++) {
            const float w = w_ih[(g * 32 + j) * 3 + d];
            wihs[g * 3 + d][j] = pack2(w, w);
        }
    {
        const float br  = bias[j];
        const float bz  = bias[32 + j];
        const float ban = bias[64 + j] + bias_n[j];
        wihs[9][j]  = pack2(br, br);
        wihs[10][j] = pack2(bz, bz);
        wihs[11][j] = pack2(ban, ban);
    }
    const u64 halfp = pack2(0.5f, 0.5f);

    float h = 0.0f;
    const float* gx   = inp + (size_t)b * (TT * 3);
    float*       gout = out + (size_t)b * TT;

    float p0 = gx[j], p1 = gx[32 + j], p2 = gx[64 + j];

    for (int t = 0; t < TT; t += 2) {
        if ((t & 31) == 0) {
            __syncwarp();                 // previous chunk's xpl readers done
            const int i0 = j, i1 = 32 + j, i2 = 64 + j;
            xpl[i0 % 3][i0 / 3] = p0;     // transpose into dim-planes
            xpl[i1 % 3][i1 / 3] = p1;
            xpl[i2 % 3][i2 / 3] = p2;
            const int nb = (t + 32) * 3;
            if (nb < TT * 3) {            // prefetch next chunk over 32 steps
                p0 = gx[nb + j];
                p1 = gx[nb + 32 + j];
                p2 = gx[nb + 64 + j];
            }
        }

        // ===== even step: publish h, sync (also makes xpl visible) =====
        hbuf[0][j] = h;
        __syncwarp();

        // Input gates for BOTH steps as f32x2 (weights via LDS.64 -> MIO pipe).
        const int s2 = (t & 31) >> 1;
        const u64 x0p = reinterpret_cast<const u64*>(xpl[0])[s2];
        const u64 x1p = reinterpret_cast<const u64*>(xpl[1])[s2];
        const u64 x2p = reinterpret_cast<const u64*>(xpl[2])[s2];
        u64 igr = wihs[9][j], igz = wihs[10][j], iga = wihs[11][j];
        ffma2(igr, wihs[0][j], x0p);
        ffma2(igz, wihs[3][j], x0p);
        ffma2(iga, wihs[6][j], x0p);
        ffma2(igr, wihs[1][j], x1p);
        ffma2(igz, wihs[4][j], x1p);
        ffma2(iga, wihs[7][j], x1p);
        ffma2(igr, wihs[2][j], x2p);
        ffma2(igz, wihs[5][j], x2p);
        ffma2(iga, wihs[8][j], x2p);
        const float2 igrf = unpack2(igr);
        const float2 igzf = unpack2(igz);
        const float2 igaf = unpack2(iga);

#pragma unroll
        for (int half = 0; half < 2; half++) {
            const float ir = half ? igrf.y : igrf.x;
            const float iz = half ? igzf.y : igzf.x;
            const float ia = half ? igaf.y : igaf.x;

            if (half) {                      // odd step publishes into buffer 1
                hbuf[1][j] = h;
                __syncwarp();
            }
            const float* cur = hbuf[half];

            // Hidden matvec: 48 dual FMAs; r/z accumulators seeded with ig.
            u64 accr = pack2(ir, 0.0f);
            u64 accz = pack2(iz, 0.0f);
            u64 acca = 0ull;                 // a-gate hidden part stays pure
            const ulonglong2* hp128 = reinterpret_cast<const ulonglong2*>(cur);
#pragma unroll
            for (int q = 0; q < 8; q++) {
                const ulonglong2 hp = hp128[q];
                ffma2(accr, wr[2 * q],     hp.x);
                ffma2(accz, wz[2 * q],     hp.x);
                ffma2(acca, wa[2 * q],     hp.x);
                ffma2(accr, wr[2 * q + 1], hp.y);
                ffma2(accz, wz[2 * q + 1], hp.y);
                ffma2(acca, wa[2 * q + 1], hp.y);
            }
            const float2 fr = unpack2(accr);
            const float2 fz = unpack2(accz);
            const float2 fa = unpack2(acca);

            // Packed r/z: one add2, one mul2, two MUFU.TANH, one fma2.
            const u64 s01 = add2(pack2(fr.x, fz.x), pack2(fr.y, fz.y));
            const float2 mf = unpack2(mul2(s01, halfp));
            const u64 rzp = fma2(pack2(tanh_hw(mf.x), tanh_hw(mf.y)), halfp, halfp);
            const float2 rzf = unpack2(rzp);
            const float r = rzf.x, z = rzf.y;

            const float n = tanh_hw(fmaf(r, fa.x + fa.y, ia));
            h = fmaf(z, h - n, n);           // (1-z)*n + z*h

            if (j == 0) gout[t + half] = h;
        }
    }
}

extern "C" void kernel_launch(void* const* d_in, const int* in_sizes, int n_in,
                              void* d_out, int out_size) {
    const float* inp    = (const float*)d_in[0];
    const float* w_ih   = (const float*)d_in[1];
    const float* w_hh   = (const float*)d_in[2];
    const float* bias   = (const float*)d_in[3];
    const float* bias_n = (const float*)d_in[4];
    float* out = (float*)d_out;
    gru_warp_kernel<<<BB, 32>>>(inp, w_ih, w_hh, bias, bias_n, out);
}

// round 9
// speedup vs baseline: 1.0174x; 1.0174x over previous
#include <cuda_runtime.h>
#include <cstdint>

// Shape: inp:[2048,2048,3] f32, w_ih:[96,3], w_hh:[96,32], bias:[96], bias_n:[32]
// out:[2048,2048,1] f32 (h[0] each step)
#define TT 2048
#define BB 2048

typedef unsigned long long u64;

__device__ __forceinline__ void ffma2(u64 &d, u64 a, u64 b) {
    asm("fma.rn.f32x2 %0, %1, %2, %0;" : "+l"(d) : "l"(a), "l"(b));
}
__device__ __forceinline__ u64 pack2(float a, float b) {
    u64 d; asm("mov.b64 %0, {%1, %2};" : "=l"(d) : "f"(a), "f"(b));
    return d;
}
__device__ __forceinline__ float2 unpack2(u64 v) {
    float2 r; asm("mov.b64 {%0, %1}, %2;" : "=f"(r.x), "=f"(r.y) : "l"(v));
    return r;
}
__device__ __forceinline__ float tanh_hw(float x) {
    float y; asm("tanh.approx.f32 %0, %1;" : "=f"(y) : "f"(x));
    return y;
}
// sigma(x) = 0.5 + 0.5*tanh(0.5x): FMUL-imm + MUFU + FFMA-imm (imm forms rt~1).
__device__ __forceinline__ float sigmoid_hw(float x) {
    return fmaf(0.5f, tanh_hw(0.5f * x), 0.5f);
}

// One warp per sequence; lane j owns hidden unit j. W_hh in regs (48 f32x2,
// rt-3 banking-paced). Input gates computed TWO steps at a time from paired
// W_ih REGISTERS (grid-bound occupancy leaves 18 regs free under the 146
// cap). r/z accumulators seeded with the input gate via alu packs. All
// activation constants are immediates. One __syncwarp per step.
__global__ void __launch_bounds__(32, 14)
gru_warp_kernel(const float* __restrict__ inp,
                const float* __restrict__ w_ih,
                const float* __restrict__ w_hh,
                const float* __restrict__ bias,
                const float* __restrict__ bias_n,
                float* __restrict__ out) {
    __shared__ __align__(16) float hbuf[2][32];
    __shared__ __align__(8)  float xpl[3][32];  // x planes: [dim][step-in-chunk]

    const int j = threadIdx.x;
    const int b = blockIdx.x;

    // ---- W_hh rows into registers ----
    u64 wr[16], wz[16], wa[16];
    {
        const u64* rr = reinterpret_cast<const u64*>(w_hh + (0 * 32 + j) * 32);
        const u64* rz = reinterpret_cast<const u64*>(w_hh + (1 * 32 + j) * 32);
        const u64* ra = reinterpret_cast<const u64*>(w_hh + (2 * 32 + j) * 32);
#pragma unroll
        for (int k = 0; k < 16; k++) { wr[k] = rr[k]; wz[k] = rz[k]; wa[k] = ra[k]; }
    }
    // ---- W_ih + biases as lane-duplicated PAIRS in registers ----
    u64 wih[9], bih[3];
#pragma unroll
    for (int g = 0; g < 3; g++)
#pragma unroll
        for (int d = 0; d < 3; d++) {
            const float w = w_ih[(g * 32 + j) * 3 + d];
            wih[g * 3 + d] = pack2(w, w);
        }
    {
        const float br  = bias[j];
        const float bz  = bias[32 + j];
        const float ban = bias[64 + j] + bias_n[j];
        bih[0] = pack2(br, br);
        bih[1] = pack2(bz, bz);
        bih[2] = pack2(ban, ban);
    }

    float h = 0.0f;
    const float* gx   = inp + (size_t)b * (TT * 3);
    float*       gout = out + (size_t)b * TT;

    float p0 = gx[j], p1 = gx[32 + j], p2 = gx[64 + j];

    for (int t = 0; t < TT; t += 2) {
        if ((t & 31) == 0) {
            __syncwarp();                 // previous chunk's xpl readers done
            const int i0 = j, i1 = 32 + j, i2 = 64 + j;
            xpl[i0 % 3][i0 / 3] = p0;     // transpose into dim-planes
            xpl[i1 % 3][i1 / 3] = p1;
            xpl[i2 % 3][i2 / 3] = p2;
            const int nb = (t + 32) * 3;
            if (nb < TT * 3) {            // prefetch next chunk over 32 steps
                p0 = gx[nb + j];
                p1 = gx[nb + 32 + j];
                p2 = gx[nb + 64 + j];
            }
        }

        hbuf[0][j] = h;                   // publish h for the even step
        __syncwarp();                     // also makes xpl visible

        // Input gates for BOTH steps as f32x2 (broadcast LDS.64 x pairs,
        // register weights). Off the critical path (depends only on x).
        const int s2 = (t & 31) >> 1;
        const u64 x0p = reinterpret_cast<const u64*>(xpl[0])[s2];
        const u64 x1p = reinterpret_cast<const u64*>(xpl[1])[s2];
        const u64 x2p = reinterpret_cast<const u64*>(xpl[2])[s2];
        u64 igr = bih[0], igz = bih[1], iga = bih[2];
        ffma2(igr, wih[0], x0p);
        ffma2(igz, wih[3], x0p);
        ffma2(iga, wih[6], x0p);
        ffma2(igr, wih[1], x1p);
        ffma2(igz, wih[4], x1p);
        ffma2(iga, wih[7], x1p);
        ffma2(igr, wih[2], x2p);
        ffma2(igz, wih[5], x2p);
        ffma2(iga, wih[8], x2p);
        const float2 igrf = unpack2(igr);
        const float2 igzf = unpack2(igz);
        const float2 igaf = unpack2(iga);

#pragma unroll
        for (int half = 0; half < 2; half++) {
            const float ir = half ? igrf.y : igrf.x;
            const float iz = half ? igzf.y : igzf.x;
            const float ia = half ? igaf.y : igaf.x;

            if (half) {                   // odd step publishes into buffer 1
                hbuf[1][j] = h;
                __syncwarp();
            }
            const float* cur = hbuf[half];

            // Hidden matvec: 48 dual FMAs; r/z accumulators seeded with the
            // input gate (pack = alu MOV, free under the fma-pipe ceiling).
            u64 accr = pack2(ir, 0.0f);
            u64 accz = pack2(iz, 0.0f);
            u64 acca = 0ull;              // a-gate hidden part stays pure
            const ulonglong2* hp128 = reinterpret_cast<const ulonglong2*>(cur);
#pragma unroll
            for (int q = 0; q < 8; q++) {
                const ulonglong2 hp = hp128[q];
                ffma2(accr, wr[2 * q],     hp.x);
                ffma2(accz, wz[2 * q],     hp.x);
                ffma2(acca, wa[2 * q],     hp.x);
                ffma2(accr, wr[2 * q + 1], hp.y);
                ffma2(accz, wz[2 * q + 1], hp.y);
                ffma2(acca, wa[2 * q + 1], hp.y);
            }
            const float2 fr = unpack2(accr);
            const float2 fz = unpack2(accz);
            const float2 fa = unpack2(acca);

            const float r = sigmoid_hw(fr.x + fr.y);   // imm-form consts
            const float z = sigmoid_hw(fz.x + fz.y);
            const float n = tanh_hw(fmaf(r, fa.x + fa.y, ia));
            h = fmaf(z, h - n, n);        // (1-z)*n + z*h

            if (j == 0) gout[t + half] = h;
        }
    }
}

extern "C" void kernel_launch(void* const* d_in, const int* in_sizes, int n_in,
                              void* d_out, int out_size) {
    const float* inp    = (const float*)d_in[0];
    const float* w_ih   = (const float*)d_in[1];
    const float* w_hh   = (const float*)d_in[2];
    const float* bias   = (const float*)d_in[3];
    const float* bias_n = (const float*)d_in[4];
    float* out = (float*)d_out;
    gru_warp_kernel<<<BB, 32>>>(inp, w_ih, w_hh, bias, bias_n, out);
}

// round 10
// speedup vs baseline: 1.0269x; 1.0094x over previous
#include <cuda_runtime.h>
#include <cuda_fp16.h>
#include <cstdint>

// Shape: inp:[2048,2048,3] f32, w_ih:[96,3], w_hh:[96,32], bias:[96], bias_n:[32]
// out:[2048,2048,1] f32 (h[0] each step)
#define TT 2048
#define BB 2048

typedef unsigned long long u64;

__device__ __forceinline__ void ffma2(u64 &d, u64 a, u64 b) {
    asm("fma.rn.f32x2 %0, %1, %2, %0;" : "+l"(d) : "l"(a), "l"(b));
}
__device__ __forceinline__ float2 unpack2(u64 v) {
    float2 r; asm("mov.b64 {%0, %1}, %2;" : "=f"(r.x), "=f"(r.y) : "l"(v));
    return r;
}
__device__ __forceinline__ float tanh_hw(float x) {
    float y; asm("tanh.approx.f32 %0, %1;" : "=f"(y) : "f"(x));
    return y;
}
// sigma(x) = 0.5 + 0.5*tanh(0.5x): imm-form FMUL/FFMA + one MUFU.TANH.
__device__ __forceinline__ float sigmoid_hw(float x) {
    return fmaf(0.5f, tanh_hw(0.5f * x), 0.5f);
}

// One warp per sequence; lane j owns hidden unit j.
// fma-pipe cycle budget is THE constraint (R6 measured exactly at the
// rt-paced floor). r/z hidden matvecs run in packed fp16 (HFMA2: 2 MACs per
// 2 cyc vs f32x2's 2 per 3) — their error passes through sigmoid slope 0.25
// and is damped by the z-carry. The a-gate matvec and the carried h state
// remain fully fp32, so recurrent error does not compound.
__global__ void __launch_bounds__(32, 14)
gru_warp_kernel(const float* __restrict__ inp,
                const float* __restrict__ w_ih,
                const float* __restrict__ w_hh,
                const float* __restrict__ bias,
                const float* __restrict__ bias_n,
                float* __restrict__ out) {
    __shared__ __align__(16) float  hbuf[2][32];   // fp32 h (a-gate)
    __shared__ __align__(16) __half hh[2][32];     // fp16 h (r/z gates)
    __shared__ float xbuf[96];                     // 32 timesteps of x

    const int j = threadIdx.x;
    const int b = blockIdx.x;

    // ---- a-gate W_hh row in f32x2 registers ----
    u64 wa[16];
    {
        const u64* ra = reinterpret_cast<const u64*>(w_hh + (2 * 32 + j) * 32);
#pragma unroll
        for (int k = 0; k < 16; k++) wa[k] = ra[k];
    }
    // ---- r/z W_hh rows as f16x2 pairs (units 2k,2k+1) ----
    __half2 wr16[16], wz16[16];
    {
        const float* rr = w_hh + (0 * 32 + j) * 32;
        const float* rz = w_hh + (1 * 32 + j) * 32;
#pragma unroll
        for (int k = 0; k < 16; k++) {
            wr16[k] = __floats2half2_rn(rr[2 * k], rr[2 * k + 1]);
            wz16[k] = __floats2half2_rn(rz[2 * k], rz[2 * k + 1]);
        }
    }
    const float wir0 = w_ih[(0 * 32 + j) * 3 + 0];
    const float wir1 = w_ih[(0 * 32 + j) * 3 + 1];
    const float wir2 = w_ih[(0 * 32 + j) * 3 + 2];
    const float wiz0 = w_ih[(1 * 32 + j) * 3 + 0];
    const float wiz1 = w_ih[(1 * 32 + j) * 3 + 1];
    const float wiz2 = w_ih[(1 * 32 + j) * 3 + 2];
    const float wia0 = w_ih[(2 * 32 + j) * 3 + 0];
    const float wia1 = w_ih[(2 * 32 + j) * 3 + 1];
    const float wia2 = w_ih[(2 * 32 + j) * 3 + 2];
    const float br  = bias[0 * 32 + j];
    const float bz  = bias[1 * 32 + j];
    const float ban = bias[2 * 32 + j] + bias_n[j];

    float h = 0.0f;
    const float* gx   = inp + (size_t)b * (TT * 3);
    float*       gout = out + (size_t)b * TT;

    float p0 = gx[j], p1 = gx[32 + j], p2 = gx[64 + j];

    for (int t = 0; t < TT; t++) {
        if ((t & 31) == 0) {
            __syncwarp();                 // previous chunk's xbuf readers done
            xbuf[j]      = p0;
            xbuf[32 + j] = p1;
            xbuf[64 + j] = p2;
            const int nb = (t + 32) * 3;
            if (nb < TT * 3) {            // prefetch next chunk over 32 steps
                p0 = gx[nb + j];
                p1 = gx[nb + 32 + j];
                p2 = gx[nb + 64 + j];
            }
        }

        // Publish h in fp32 (a-gate) and fp16 (r/z), then broadcast back.
        const int par = t & 1;
        hbuf[par][j] = h;
        hh[par][j]   = __float2half(h);
        __syncwarp();

        // Input gates (fp32 scalar; off the critical path).
        const int ti = (t & 31) * 3;
        const float x0 = xbuf[ti + 0];
        const float x1 = xbuf[ti + 1];
        const float x2 = xbuf[ti + 2];
        const float ir = fmaf(wir2, x2, fmaf(wir1, x1, fmaf(wir0, x0, br)));
        const float iz = fmaf(wiz2, x2, fmaf(wiz1, x1, fmaf(wiz0, x0, bz)));
        const float ia = fmaf(wia2, x2, fmaf(wia1, x1, fmaf(wia0, x0, ban)));

        // a-gate matvec: fp32 (16 dual FMAs), h via 8 LDS.128.
        u64 acca = 0ull;
        const ulonglong2* hp128 =
            reinterpret_cast<const ulonglong2*>(hbuf[par]);
#pragma unroll
        for (int q = 0; q < 8; q++) {
            const ulonglong2 hp = hp128[q];
            ffma2(acca, wa[2 * q],     hp.x);
            ffma2(acca, wa[2 * q + 1], hp.y);
        }

        // r/z matvecs: fp16x2 (32 HFMA2), h2 via 4 LDS.128.
        __half2 accr2 = __float2half2_rn(0.0f);
        __half2 accz2 = __float2half2_rn(0.0f);
        const uint4* hv = reinterpret_cast<const uint4*>(hh[par]);
#pragma unroll
        for (int q = 0; q < 4; q++) {
            const uint4 v = hv[q];
            const __half2 h0 = *reinterpret_cast<const __half2*>(&v.x);
            const __half2 h1 = *reinterpret_cast<const __half2*>(&v.y);
            const __half2 h2 = *reinterpret_cast<const __half2*>(&v.z);
            const __half2 h3 = *reinterpret_cast<const __half2*>(&v.w);
            accr2 = __hfma2(wr16[4 * q + 0], h0, accr2);
            accz2 = __hfma2(wz16[4 * q + 0], h0, accz2);
            accr2 = __hfma2(wr16[4 * q + 1], h1, accr2);
            accz2 = __hfma2(wz16[4 * q + 1], h1, accz2);
            accr2 = __hfma2(wr16[4 * q + 2], h2, accr2);
            accz2 = __hfma2(wz16[4 * q + 2], h2, accz2);
            accr2 = __hfma2(wr16[4 * q + 3], h3, accr2);
            accz2 = __hfma2(wz16[4 * q + 3], h3, accz2);
        }
        const float2 frh = __half22float2(accr2);
        const float2 fzh = __half22float2(accz2);
        const float2 fa  = unpack2(acca);

        const float r = sigmoid_hw(ir + (frh.x + frh.y));
        const float z = sigmoid_hw(iz + (fzh.x + fzh.y));
        const float n = tanh_hw(fmaf(r, fa.x + fa.y, ia));
        h = fmaf(z, h - n, n);            // (1-z)*n + z*h

        if (j == 0) gout[t] = h;
    }
}

extern "C" void kernel_launch(void* const* d_in, const int* in_sizes, int n_in,
                              void* d_out, int out_size) {
    const float* inp    = (const float*)d_in[0];
    const float* w_ih   = (const float*)d_in[1];
    const float* w_hh   = (const float*)d_in[2];
    const float* bias   = (const float*)d_in[3];
    const float* bias_n = (const float*)d_in[4];
    float* out = (float*)d_out;
    gru_warp_kernel<<<BB, 32>>>(inp, w_ih, w_hh, bias, bias_n, out);
}